// round 5
// baseline (speedup 1.0000x reference)
#include <cuda_runtime.h>

#define N_NODES 200000
#define N_EDGES 6400000
#define F_IN 20
#define F_OUT 10
#define XP_STRIDE 12           // 10 floats padded to 48B so rows are float4-aligned
#define BN_EPS 1e-5f

// ---------------- device scratch (no allocations allowed) ----------------
__device__ float g_sum[F_IN];                                   // BN feature sums
__device__ float g_sq[F_IN];                                    // BN feature sum of squares
__device__ float g_wsum;                                        // sum of edge weights
__device__ float g_as[N_NODES];                                 // per-node src attention term
__device__ float g_ad[N_NODES];                                 // per-node dst attention term
__device__ __align__(16) float g_xp[(size_t)N_NODES * XP_STRIDE];  // projected features
__device__ float4 g_acc[(size_t)N_NODES * 3];                   // [num0..3][num4..7][num8,num9,den,-]

// Vector reduction into global memory: red.global.add.v4.f32.
// Explicit .global qualifier required — generic-space vector atomics trap on sm_103a.
__device__ __forceinline__ void red_add_v4(float4* addr, float a, float b, float c, float d) {
    asm volatile("red.global.add.v4.f32 [%0], {%1, %2, %3, %4};"
                 :: "l"(addr), "f"(a), "f"(b), "f"(c), "f"(d)
                 : "memory");
}

// ---------------- kernel 0: zero accumulators ----------------
__global__ void k_zero() {
    size_t stride = (size_t)gridDim.x * blockDim.x;
    size_t total = (size_t)N_NODES * 3;
    for (size_t i = (size_t)blockIdx.x * blockDim.x + threadIdx.x; i < total; i += stride)
        g_acc[i] = make_float4(0.f, 0.f, 0.f, 0.f);
    if (blockIdx.x == 0) {
        if (threadIdx.x < F_IN) { g_sum[threadIdx.x] = 0.f; g_sq[threadIdx.x] = 0.f; }
        if (threadIdx.x == 32) g_wsum = 0.f;
    }
}

// ---------------- kernel 1: BN batch statistics ----------------
__global__ void k_bn_stats(const float* __restrict__ h) {
    __shared__ float red[8][2 * F_IN];
    int i = blockIdx.x * blockDim.x + threadIdx.x;
    int lane = threadIdx.x & 31;
    int warp = threadIdx.x >> 5;

    float v[F_IN];
#pragma unroll
    for (int f = 0; f < F_IN; f++) v[f] = 0.f;
    if (i < N_NODES) {
#pragma unroll
        for (int f = 0; f < F_IN; f++) v[f] = h[(size_t)i * F_IN + f];
    }
#pragma unroll
    for (int f = 0; f < F_IN; f++) {
        float sv = v[f];
        float qv = v[f] * v[f];
#pragma unroll
        for (int o = 16; o > 0; o >>= 1) {
            sv += __shfl_down_sync(0xffffffffu, sv, o);
            qv += __shfl_down_sync(0xffffffffu, qv, o);
        }
        if (lane == 0) { red[warp][f] = sv; red[warp][F_IN + f] = qv; }
    }
    __syncthreads();
    int j = threadIdx.x;
    if (j < 2 * F_IN) {
        float t = 0.f;
#pragma unroll
        for (int w = 0; w < 8; w++) t += red[w][j];
        if (j < F_IN) atomicAdd(&g_sum[j], t);
        else          atomicAdd(&g_sq[j - F_IN], t);
    }
}

// ---------------- kernel 2: BN + projection + attention terms ----------------
__global__ void k_node_pre(const float* __restrict__ h,
                           const float* __restrict__ bn_w, const float* __restrict__ bn_b,
                           const float* __restrict__ W,
                           const float* __restrict__ att_src, const float* __restrict__ att_dst) {
    __shared__ float s_mu[F_IN], s_rs[F_IN], s_bw[F_IN], s_bb[F_IN];
    __shared__ float s_W[F_OUT * F_IN], s_as[F_OUT], s_ad[F_OUT];
    int t = threadIdx.x;
    if (t < F_IN) {
        float mu = g_sum[t] * (1.f / N_NODES);
        float var = g_sq[t] * (1.f / N_NODES) - mu * mu;
        s_mu[t] = mu;
        s_rs[t] = rsqrtf(var + BN_EPS);
        s_bw[t] = bn_w[t];
        s_bb[t] = bn_b[t];
    }
    if (t < F_OUT) { s_as[t] = att_src[t]; s_ad[t] = att_dst[t]; }
    for (int k = t; k < F_OUT * F_IN; k += blockDim.x) s_W[k] = W[k];
    __syncthreads();

    int i = blockIdx.x * blockDim.x + t;
    if (i >= N_NODES) return;

    float xn[F_IN];
#pragma unroll
    for (int f = 0; f < F_IN; f++)
        xn[f] = (h[(size_t)i * F_IN + f] - s_mu[f]) * s_rs[f] * s_bw[f] + s_bb[f];

    float as = 0.f, ad = 0.f;
    float* xr = g_xp + (size_t)i * XP_STRIDE;
#pragma unroll
    for (int o = 0; o < F_OUT; o++) {
        float acc = 0.f;
#pragma unroll
        for (int k = 0; k < F_IN; k++) acc += xn[k] * s_W[o * F_IN + k];
        xr[o] = acc;
        as += acc * s_as[o];
        ad += acc * s_ad[o];
    }
    g_as[i] = as;
    g_ad[i] = ad;
}

// ---------------- kernel 3: edge pass (softmax numer/denom accumulation) ----------------
__global__ void k_edges(const int* __restrict__ ei,
                        const float* __restrict__ ew,
                        const float* __restrict__ W_edge,
                        const float* __restrict__ att_edge) {
    __shared__ float s_w[8];
    float c = 0.f;
#pragma unroll
    for (int f = 0; f < F_OUT; f++) c += W_edge[f] * att_edge[f];

    float wacc = 0.f;
    int stride = gridDim.x * blockDim.x;
    for (int e = blockIdx.x * blockDim.x + threadIdx.x; e < N_EDGES; e += stride) {
        int s = ei[e];
        int d = ei[N_EDGES + e];
        float w = ew[e];
        wacc += w;
        float l = g_as[s] + g_ad[d] + c * w;
        l = fmaxf(l, 0.2f * l);           // leaky_relu(l, 0.2)
        float ex = __expf(l);

        const float4* xr = (const float4*)(g_xp + (size_t)s * XP_STRIDE);
        float4 x0 = xr[0];
        float4 x1 = xr[1];
        float4 x2 = xr[2];                // x2.x,x2.y valid; z,w are pad

        float4* ab = &g_acc[(size_t)d * 3];
        red_add_v4(&ab[0], ex * x0.x, ex * x0.y, ex * x0.z, ex * x0.w);
        red_add_v4(&ab[1], ex * x1.x, ex * x1.y, ex * x1.z, ex * x1.w);
        red_add_v4(&ab[2], ex * x2.x, ex * x2.y, ex, 0.f);
    }

    // block-reduce edge weight sum (for self-loop fill_value='mean')
#pragma unroll
    for (int o = 16; o > 0; o >>= 1) wacc += __shfl_down_sync(0xffffffffu, wacc, o);
    if ((threadIdx.x & 31) == 0) s_w[threadIdx.x >> 5] = wacc;
    __syncthreads();
    if (threadIdx.x == 0) {
        float t = 0.f;
#pragma unroll
        for (int w = 0; w < 8; w++) t += s_w[w];
        atomicAdd(&g_wsum, t);
    }
}

// ---------------- kernel 4: self-loop + normalize + bias + MLP + outputs ----------------
__global__ void k_node_post(const float* __restrict__ W_edge, const float* __restrict__ att_edge,
                            const float* __restrict__ bias,
                            const float* __restrict__ fc1w, const float* __restrict__ fc1b,
                            const float* __restrict__ fc2w, const float* __restrict__ fc2b,
                            const float* __restrict__ fc3w, const float* __restrict__ fc3b,
                            float* __restrict__ out) {
    __shared__ float s1[F_OUT * F_OUT], s2[F_OUT * F_OUT], s3[F_OUT * F_OUT];
    __shared__ float b1[F_OUT], b2[F_OUT], b3[F_OUT], sb[F_OUT];
    int t = threadIdx.x;
    for (int k = t; k < F_OUT * F_OUT; k += blockDim.x) {
        s1[k] = fc1w[k]; s2[k] = fc2w[k]; s3[k] = fc3w[k];
    }
    if (t < F_OUT) { b1[t] = fc1b[t]; b2[t] = fc2b[t]; b3[t] = fc3b[t]; sb[t] = bias[t]; }
    __syncthreads();

    float c = 0.f;
#pragma unroll
    for (int f = 0; f < F_OUT; f++) c += W_edge[f] * att_edge[f];
    float wbar = g_wsum * (1.f / N_EDGES);

    int i = blockIdx.x * blockDim.x + t;
    if (i >= N_NODES) return;

    // self loop: src = dst = i
    float l = g_as[i] + g_ad[i] + c * wbar;
    l = fmaxf(l, 0.2f * l);
    float exl = __expf(l);

    const float4* ab = &g_acc[(size_t)i * 3];
    float4 A0 = ab[0], A1 = ab[1], A2 = ab[2];
    const float* xr = g_xp + (size_t)i * XP_STRIDE;

    float num[F_OUT];
    num[0] = A0.x; num[1] = A0.y; num[2] = A0.z; num[3] = A0.w;
    num[4] = A1.x; num[5] = A1.y; num[6] = A1.z; num[7] = A1.w;
    num[8] = A2.x; num[9] = A2.y;
    float den = A2.z + exl;
    float rden = 1.f / den;

    float o[F_OUT];
#pragma unroll
    for (int f = 0; f < F_OUT; f++)
        o[f] = (num[f] + exl * xr[f]) * rden + sb[f];

    // embeddings = relu(out)
    float* emb = out + (size_t)i * F_OUT;
#pragma unroll
    for (int f = 0; f < F_OUT; f++) emb[f] = fmaxf(o[f], 0.f);

    // MLP: y = relu(relu(o @ fc1.T + b1) @ fc2.T + b2) @ fc3.T + b3
    float y1[F_OUT], y2[F_OUT];
#pragma unroll
    for (int f = 0; f < F_OUT; f++) {
        float acc = b1[f];
#pragma unroll
        for (int k = 0; k < F_OUT; k++) acc += o[k] * s1[f * F_OUT + k];
        y1[f] = fmaxf(acc, 0.f);
    }
#pragma unroll
    for (int f = 0; f < F_OUT; f++) {
        float acc = b2[f];
#pragma unroll
        for (int k = 0; k < F_OUT; k++) acc += y1[k] * s2[f * F_OUT + k];
        y2[f] = fmaxf(acc, 0.f);
    }
    float* yo = out + (size_t)N_NODES * F_OUT + (size_t)i * F_OUT;
#pragma unroll
    for (int f = 0; f < F_OUT; f++) {
        float acc = b3[f];
#pragma unroll
        for (int k = 0; k < F_OUT; k++) acc += y2[k] * s3[f * F_OUT + k];
        yo[f] = acc;
    }
}

// ---------------- launch ----------------
extern "C" void kernel_launch(void* const* d_in, const int* in_sizes, int n_in,
                              void* d_out, int out_size) {
    const float* h        = (const float*)d_in[0];
    const int*   ei       = (const int*)d_in[1];     // JAX x64-disabled: int64 request -> int32 buffer
    const float* ew       = (const float*)d_in[2];
    const float* bn_w     = (const float*)d_in[3];
    const float* bn_b     = (const float*)d_in[4];
    const float* W        = (const float*)d_in[5];
    const float* att_src  = (const float*)d_in[6];
    const float* att_dst  = (const float*)d_in[7];
    const float* att_edge = (const float*)d_in[8];
    const float* W_edge   = (const float*)d_in[9];
    const float* bias     = (const float*)d_in[10];
    const float* fc1w     = (const float*)d_in[11];
    const float* fc1b     = (const float*)d_in[12];
    const float* fc2w     = (const float*)d_in[13];
    const float* fc2b     = (const float*)d_in[14];
    const float* fc3w     = (const float*)d_in[15];
    const float* fc3b     = (const float*)d_in[16];
    float* out = (float*)d_out;

    const int TPB = 256;
    const int node_blocks = (N_NODES + TPB - 1) / TPB;

    k_zero<<<1184, TPB>>>();
    k_bn_stats<<<node_blocks, TPB>>>(h);
    k_node_pre<<<node_blocks, TPB>>>(h, bn_w, bn_b, W, att_src, att_dst);
    k_edges<<<1184, TPB>>>(ei, ew, W_edge, att_edge);
    k_node_post<<<node_blocks, TPB>>>(W_edge, att_edge, bias,
                                      fc1w, fc1b, fc2w, fc2b, fc3w, fc3b, out);
}

// round 8
// speedup vs baseline: 1.1711x; 1.1711x over previous
#include <cuda_runtime.h>
#include <cuda_fp16.h>

#define N_NODES 200000
#define N_EDGES 6400000
#define F_IN 20
#define F_OUT 10
#define XP_STRIDE 12           // fp32 copy for self-loop use (node_post)
#define BN_EPS 1e-5f

// ---------------- device scratch (no allocations allowed) ----------------
__device__ float g_sum[F_IN];
__device__ float g_sq[F_IN];
__device__ float g_wsum;
__device__ float g_ad[N_NODES];                                  // dst attention term (fp32)

// src-side packed payload: exactly one 32B sector per node:
//   a.x..a.w = h2(x0,x1) h2(x2,x3) h2(x4,x5) h2(x6,x7)
//   b.x      = h2(x8,x9), b.y = a_s (fp32), b.z/b.w = pad
struct __align__(32) SrcPack { float4 a; float4 b; };
__device__ SrcPack g_sx[N_NODES];

__device__ float g_as_self[N_NODES];                             // fp32 a_s for self loop
__device__ __align__(16) float g_xp[(size_t)N_NODES * XP_STRIDE];
__device__ float4 g_acc[(size_t)N_NODES * 3];                    // [num0..3][num4..7][num8,num9,den,-]

__device__ __forceinline__ void red_add_v4(float4* addr, float a, float b, float c, float d) {
    asm volatile("red.global.add.v4.f32 [%0], {%1, %2, %3, %4};"
                 :: "l"(addr), "f"(a), "f"(b), "f"(c), "f"(d)
                 : "memory");
}

__device__ __forceinline__ unsigned pk2(float a, float b) {
    __half2 h = __floats2half2_rn(a, b);
    return *reinterpret_cast<unsigned*>(&h);
}
__device__ __forceinline__ float2 up2(float fbits) {
    unsigned u = __float_as_uint(fbits);
    __half2 h = *reinterpret_cast<__half2*>(&u);
    return __half22float2(h);
}

// ---------------- kernel 0: zero accumulators ----------------
__global__ void k_zero() {
    size_t stride = (size_t)gridDim.x * blockDim.x;
    size_t total = (size_t)N_NODES * 3;
    for (size_t i = (size_t)blockIdx.x * blockDim.x + threadIdx.x; i < total; i += stride)
        g_acc[i] = make_float4(0.f, 0.f, 0.f, 0.f);
    if (blockIdx.x == 0) {
        if (threadIdx.x < F_IN) { g_sum[threadIdx.x] = 0.f; g_sq[threadIdx.x] = 0.f; }
        if (threadIdx.x == 32) g_wsum = 0.f;
    }
}

// ---------------- kernel 1: BN batch statistics ----------------
__global__ void k_bn_stats(const float* __restrict__ h) {
    __shared__ float red[8][2 * F_IN];
    int i = blockIdx.x * blockDim.x + threadIdx.x;
    int lane = threadIdx.x & 31;
    int warp = threadIdx.x >> 5;

    float v[F_IN];
#pragma unroll
    for (int f = 0; f < F_IN; f++) v[f] = 0.f;
    if (i < N_NODES) {
#pragma unroll
        for (int f = 0; f < F_IN; f++) v[f] = h[(size_t)i * F_IN + f];
    }
#pragma unroll
    for (int f = 0; f < F_IN; f++) {
        float sv = v[f];
        float qv = v[f] * v[f];
#pragma unroll
        for (int o = 16; o > 0; o >>= 1) {
            sv += __shfl_down_sync(0xffffffffu, sv, o);
            qv += __shfl_down_sync(0xffffffffu, qv, o);
        }
        if (lane == 0) { red[warp][f] = sv; red[warp][F_IN + f] = qv; }
    }
    __syncthreads();
    int j = threadIdx.x;
    if (j < 2 * F_IN) {
        float t = 0.f;
#pragma unroll
        for (int w = 0; w < 8; w++) t += red[w][j];
        if (j < F_IN) atomicAdd(&g_sum[j], t);
        else          atomicAdd(&g_sq[j - F_IN], t);
    }
}

// ---------------- kernel 2: BN + projection + attention terms ----------------
__global__ void k_node_pre(const float* __restrict__ h,
                           const float* __restrict__ bn_w, const float* __restrict__ bn_b,
                           const float* __restrict__ W,
                           const float* __restrict__ att_src, const float* __restrict__ att_dst) {
    __shared__ float s_mu[F_IN], s_rs[F_IN], s_bw[F_IN], s_bb[F_IN];
    __shared__ float s_W[F_OUT * F_IN], s_as[F_OUT], s_ad[F_OUT];
    int t = threadIdx.x;
    if (t < F_IN) {
        float mu = g_sum[t] * (1.f / N_NODES);
        float var = g_sq[t] * (1.f / N_NODES) - mu * mu;
        s_mu[t] = mu;
        s_rs[t] = rsqrtf(var + BN_EPS);
        s_bw[t] = bn_w[t];
        s_bb[t] = bn_b[t];
    }
    if (t < F_OUT) { s_as[t] = att_src[t]; s_ad[t] = att_dst[t]; }
    for (int k = t; k < F_OUT * F_IN; k += blockDim.x) s_W[k] = W[k];
    __syncthreads();

    int i = blockIdx.x * blockDim.x + t;
    if (i >= N_NODES) return;

    float xn[F_IN];
#pragma unroll
    for (int f = 0; f < F_IN; f++)
        xn[f] = (h[(size_t)i * F_IN + f] - s_mu[f]) * s_rs[f] * s_bw[f] + s_bb[f];

    float as = 0.f, ad = 0.f;
    float a[F_OUT];
    float* xr = g_xp + (size_t)i * XP_STRIDE;
#pragma unroll
    for (int o = 0; o < F_OUT; o++) {
        float acc = 0.f;
#pragma unroll
        for (int k = 0; k < F_IN; k++) acc += xn[k] * s_W[o * F_IN + k];
        a[o] = acc;
        xr[o] = acc;
        as += acc * s_as[o];
        ad += acc * s_ad[o];
    }
    g_as_self[i] = as;
    g_ad[i] = ad;

    SrcPack p;
    p.a.x = __uint_as_float(pk2(a[0], a[1]));
    p.a.y = __uint_as_float(pk2(a[2], a[3]));
    p.a.z = __uint_as_float(pk2(a[4], a[5]));
    p.a.w = __uint_as_float(pk2(a[6], a[7]));
    p.b.x = __uint_as_float(pk2(a[8], a[9]));
    p.b.y = as;
    p.b.z = 0.f;
    p.b.w = 0.f;
    g_sx[i] = p;
}

// ---------------- kernel 3: edge pass ----------------
__global__ void k_edges(const int* __restrict__ ei,
                        const float* __restrict__ ew,
                        const float* __restrict__ W_edge,
                        const float* __restrict__ att_edge) {
    __shared__ float s_w[8];
    float c = 0.f;
#pragma unroll
    for (int f = 0; f < F_OUT; f++) c += W_edge[f] * att_edge[f];

    float wacc = 0.f;
    int stride = gridDim.x * blockDim.x;
#pragma unroll 4
    for (int e = blockIdx.x * blockDim.x + threadIdx.x; e < N_EDGES; e += stride) {
        int s = ei[e];
        int d = ei[N_EDGES + e];
        float w = ew[e];
        wacc += w;

        const float4* sx = &g_sx[s].a;
        float4 p0 = sx[0];
        float4 p1 = sx[1];

        float l = p1.y + g_ad[d] + c * w;
        l = fmaxf(l, 0.2f * l);            // leaky_relu(l, 0.2)
        float ex = __expf(l);

        float2 x01 = up2(p0.x);
        float2 x23 = up2(p0.y);
        float2 x45 = up2(p0.z);
        float2 x67 = up2(p0.w);
        float2 x89 = up2(p1.x);

        float4* ab = &g_acc[(size_t)d * 3];
        red_add_v4(&ab[0], ex * x01.x, ex * x01.y, ex * x23.x, ex * x23.y);
        red_add_v4(&ab[1], ex * x45.x, ex * x45.y, ex * x67.x, ex * x67.y);
        red_add_v4(&ab[2], ex * x89.x, ex * x89.y, ex, 0.f);
    }

#pragma unroll
    for (int o = 16; o > 0; o >>= 1) wacc += __shfl_down_sync(0xffffffffu, wacc, o);
    if ((threadIdx.x & 31) == 0) s_w[threadIdx.x >> 5] = wacc;
    __syncthreads();
    if (threadIdx.x == 0) {
        float t = 0.f;
#pragma unroll
        for (int w = 0; w < 8; w++) t += s_w[w];
        atomicAdd(&g_wsum, t);
    }
}

// ---------------- kernel 4: self-loop + normalize + bias + MLP + outputs ----------------
__global__ void k_node_post(const float* __restrict__ W_edge, const float* __restrict__ att_edge,
                            const float* __restrict__ bias,
                            const float* __restrict__ fc1w, const float* __restrict__ fc1b,
                            const float* __restrict__ fc2w, const float* __restrict__ fc2b,
                            const float* __restrict__ fc3w, const float* __restrict__ fc3b,
                            float* __restrict__ out) {
    __shared__ float s1[F_OUT * F_OUT], s2[F_OUT * F_OUT], s3[F_OUT * F_OUT];
    __shared__ float b1[F_OUT], b2[F_OUT], b3[F_OUT], sb[F_OUT];
    int t = threadIdx.x;
    for (int k = t; k < F_OUT * F_OUT; k += blockDim.x) {
        s1[k] = fc1w[k]; s2[k] = fc2w[k]; s3[k] = fc3w[k];
    }
    if (t < F_OUT) { b1[t] = fc1b[t]; b2[t] = fc2b[t]; b3[t] = fc3b[t]; sb[t] = bias[t]; }
    __syncthreads();

    float c = 0.f;
#pragma unroll
    for (int f = 0; f < F_OUT; f++) c += W_edge[f] * att_edge[f];
    float wbar = g_wsum * (1.f / N_EDGES);

    int i = blockIdx.x * blockDim.x + t;
    if (i >= N_NODES) return;

    float l = g_as_self[i] + g_ad[i] + c * wbar;
    l = fmaxf(l, 0.2f * l);
    float exl = __expf(l);

    const float4* ab = &g_acc[(size_t)i * 3];
    float4 A0 = ab[0], A1 = ab[1], A2 = ab[2];
    const float* xr = g_xp + (size_t)i * XP_STRIDE;

    float num[F_OUT];
    num[0] = A0.x; num[1] = A0.y; num[2] = A0.z; num[3] = A0.w;
    num[4] = A1.x; num[5] = A1.y; num[6] = A1.z; num[7] = A1.w;
    num[8] = A2.x; num[9] = A2.y;
    float den = A2.z + exl;
    float rden = 1.f / den;

    float o[F_OUT];
#pragma unroll
    for (int f = 0; f < F_OUT; f++)
        o[f] = (num[f] + exl * xr[f]) * rden + sb[f];

    float* emb = out + (size_t)i * F_OUT;
#pragma unroll
    for (int f = 0; f < F_OUT; f++) emb[f] = fmaxf(o[f], 0.f);

    float y1[F_OUT], y2[F_OUT];
#pragma unroll
    for (int f = 0; f < F_OUT; f++) {
        float acc = b1[f];
#pragma unroll
        for (int k = 0; k < F_OUT; k++) acc += o[k] * s1[f * F_OUT + k];
        y1[f] = fmaxf(acc, 0.f);
    }
#pragma unroll
    for (int f = 0; f < F_OUT; f++) {
        float acc = b2[f];
#pragma unroll
        for (int k = 0; k < F_OUT; k++) acc += y1[k] * s2[f * F_OUT + k];
        y2[f] = fmaxf(acc, 0.f);
    }
    float* yo = out + (size_t)N_NODES * F_OUT + (size_t)i * F_OUT;
#pragma unroll
    for (int f = 0; f < F_OUT; f++) {
        float acc = b3[f];
#pragma unroll
        for (int k = 0; k < F_OUT; k++) acc += y2[k] * s3[f * F_OUT + k];
        yo[f] = acc;
    }
}

// ---------------- launch ----------------
extern "C" void kernel_launch(void* const* d_in, const int* in_sizes, int n_in,
                              void* d_out, int out_size) {
    const float* h        = (const float*)d_in[0];
    const int*   ei       = (const int*)d_in[1];
    const float* ew       = (const float*)d_in[2];
    const float* bn_w     = (const float*)d_in[3];
    const float* bn_b     = (const float*)d_in[4];
    const float* W        = (const float*)d_in[5];
    const float* att_src  = (const float*)d_in[6];
    const float* att_dst  = (const float*)d_in[7];
    const float* att_edge = (const float*)d_in[8];
    const float* W_edge   = (const float*)d_in[9];
    const float* bias     = (const float*)d_in[10];
    const float* fc1w     = (const float*)d_in[11];
    const float* fc1b     = (const float*)d_in[12];
    const float* fc2w     = (const float*)d_in[13];
    const float* fc2b     = (const float*)d_in[14];
    const float* fc3w     = (const float*)d_in[15];
    const float* fc3b     = (const float*)d_in[16];
    float* out = (float*)d_out;

    const int TPB = 256;
    const int node_blocks = (N_NODES + TPB - 1) / TPB;

    k_zero<<<1184, TPB>>>();
    k_bn_stats<<<node_blocks, TPB>>>(h);
    k_node_pre<<<node_blocks, TPB>>>(h, bn_w, bn_b, W, att_src, att_dst);
    k_edges<<<1184, TPB>>>(ei, ew, W_edge, att_edge);
    k_node_post<<<node_blocks, TPB>>>(W_edge, att_edge, bias,
                                      fc1w, fc1b, fc2w, fc2b, fc3w, fc3b, out);
}